// round 1
// baseline (speedup 1.0000x reference)
#include <cuda_runtime.h>

// out[i] = floorf(image[i] * 0.5f)  — pure HBM-bound streaming op.
// text_bits (d_in[1]) is unused per the reference semantics.

__global__ void __launch_bounds__(256) stego_halve_kernel(
    const float4* __restrict__ in, float4* __restrict__ out, int n4)
{
    int i = blockIdx.x * blockDim.x + threadIdx.x;
    if (i < n4) {
        float4 v = in[i];
        float4 r;
        r.x = floorf(v.x * 0.5f);
        r.y = floorf(v.y * 0.5f);
        r.z = floorf(v.z * 0.5f);
        r.w = floorf(v.w * 0.5f);
        out[i] = r;
    }
}

extern "C" void kernel_launch(void* const* d_in, const int* in_sizes, int n_in,
                              void* d_out, int out_size)
{
    const float* img = (const float*)d_in[0];
    float* out = (float*)d_out;
    int n = in_sizes[0];           // 25,165,824 — divisible by 4
    int n4 = n / 4;
    int threads = 256;
    int blocks = (n4 + threads - 1) / threads;
    stego_halve_kernel<<<blocks, threads>>>((const float4*)img, (float4*)out, n4);
}